// round 3
// baseline (speedup 1.0000x reference)
#include <cuda_runtime.h>

// Global scratch for the 5-bin (T+1, T<=7) collector histogram.
// __device__ global (no allocations allowed).
__device__ unsigned long long g_hist[8];

__global__ void hx_init_hist() {
    if (threadIdx.x < 8) g_hist[threadIdx.x] = 0ULL;
}

// Fused: passthrough copy of spikes -> out AND per-element collector sum
// histogram in one streaming pass. Fast path for T==4 with float4 vectors.
__global__ void __launch_bounds__(256) hx_main(
    const float* __restrict__ inF,
    float* __restrict__ outF,
    const int* __restrict__ time_ptr,
    long long N)
{
    const int T = (time_ptr != nullptr) ? __ldg(time_ptr) : 4;
    const long long S = N / (long long)T;   // elements per timestep
    const long long gsz = (long long)gridDim.x * blockDim.x;
    const long long tid0 = (long long)blockIdx.x * blockDim.x + threadIdx.x;

    __shared__ unsigned long long sh[8];
    if (threadIdx.x < 8) sh[threadIdx.x] = 0ULL;
    __syncthreads();

    if (T == 4 && (S & 3LL) == 0) {
        // ---- fast path: T=4, float4 vectorized ----
        const float4* __restrict__ in = (const float4*)inF;
        float4* __restrict__ out = (float4*)outF;
        const long long V = S >> 2;  // float4 elements per timestep

        int h0 = 0, h1 = 0, h2 = 0, h3 = 0, h4 = 0;

        for (long long i = tid0; i < V; i += gsz) {
            float4 a = in[i];
            float4 b = in[i + V];
            float4 c = in[i + 2 * V];
            float4 d = in[i + 3 * V];
            out[i]         = a;
            out[i + V]     = b;
            out[i + 2 * V] = c;
            out[i + 3 * V] = d;

            int s;
            s = (int)(a.x + b.x + c.x + d.x);
            h0 += (s == 0); h1 += (s == 1); h2 += (s == 2); h3 += (s == 3); h4 += (s == 4);
            s = (int)(a.y + b.y + c.y + d.y);
            h0 += (s == 0); h1 += (s == 1); h2 += (s == 2); h3 += (s == 3); h4 += (s == 4);
            s = (int)(a.z + b.z + c.z + d.z);
            h0 += (s == 0); h1 += (s == 1); h2 += (s == 2); h3 += (s == 3); h4 += (s == 4);
            s = (int)(a.w + b.w + c.w + d.w);
            h0 += (s == 0); h1 += (s == 1); h2 += (s == 2); h3 += (s == 3); h4 += (s == 4);
        }

        int hv[5] = {h0, h1, h2, h3, h4};
#pragma unroll
        for (int b = 0; b < 5; ++b) {
            int v = hv[b];
#pragma unroll
            for (int o = 16; o; o >>= 1) v += __shfl_down_sync(0xffffffffu, v, o);
            if ((threadIdx.x & 31) == 0) atomicAdd(&sh[b], (unsigned long long)v);
        }
        __syncthreads();
        if (threadIdx.x < 5) atomicAdd(&g_hist[threadIdx.x], sh[threadIdx.x]);
    } else {
        // ---- generic scalar path (T <= 7) ----
        int h[8];
#pragma unroll
        for (int b = 0; b < 8; ++b) h[b] = 0;

        for (long long i = tid0; i < S; i += gsz) {
            float s = 0.f;
            for (int t = 0; t < T; ++t) {
                float v = inF[i + (long long)t * S];
                outF[i + (long long)t * S] = v;
                s += v;
            }
            int si = (int)s;
#pragma unroll
            for (int b = 0; b < 8; ++b) h[b] += (si == b);
        }

#pragma unroll
        for (int b = 0; b < 8; ++b) {
            int v = h[b];
#pragma unroll
            for (int o = 16; o; o >>= 1) v += __shfl_down_sync(0xffffffffu, v, o);
            if ((threadIdx.x & 31) == 0) atomicAdd(&sh[b], (unsigned long long)v);
        }
        __syncthreads();
        if (threadIdx.x < 8) atomicAdd(&g_hist[threadIdx.x], sh[threadIdx.x]);
    }
}

// Single-thread finalize: derive all scalar stats from the histogram.
__global__ void hx_finalize(float* __restrict__ out, long long N,
                            const int* __restrict__ time_ptr, long long out_size)
{
    if (blockIdx.x != 0 || threadIdx.x != 0) return;
    const int T = (time_ptr != nullptr) ? *time_ptr : 4;
    const long long S = N / (long long)T;
    if (out_size < N + (long long)T + 3) return;  // layout mismatch guard

    double ones = 0.0;
    for (int k = 0; k <= T; ++k) ones += (double)k * (double)g_hist[k];

    // sparsity_ratio = total zero fraction over the whole [T,...] tensor
    out[N]     = (float)(((double)N - ones) / (double)N);
    // final-collector zero fraction
    out[N + 1] = (float)((double)g_hist[0] / (double)S);
    // bincount(collector, length=T+1)
    for (int k = 0; k <= T; ++k)
        out[N + 2 + k] = (float)g_hist[k];
}

extern "C" void kernel_launch(void* const* d_in, const int* in_sizes, int n_in,
                              void* d_out, int out_size)
{
    const float* spikes = (const float*)d_in[0];
    const int* time_ptr = (n_in > 1) ? (const int*)d_in[1] : nullptr;
    const long long N = (long long)in_sizes[0];

    hx_init_hist<<<1, 32>>>();

    const int threads = 256;
    // Upper bound on work items (vec path): N/4 per-step float4s is <= N/4 total.
    long long maxItems = (N + 3) / 4;
    int blocks = (int)(((maxItems + threads - 1) / threads < 1184)
                           ? (maxItems + threads - 1) / threads
                           : 1184);
    if (blocks < 1) blocks = 1;

    hx_main<<<blocks, threads>>>(spikes, (float*)d_out, time_ptr, N);
    hx_finalize<<<1, 1>>>((float*)d_out, N, time_ptr, (long long)out_size);
}

// round 4
// speedup vs baseline: 1.0862x; 1.0862x over previous
#include <cuda_runtime.h>

// Zero-initialized device globals (no allocations allowed).
// Reset-after-use inside the kernel keeps every launch identical,
// so the kernel is deterministic under CUDA-graph replay.
__device__ unsigned long long g_hist[8];
__device__ unsigned int       g_done;

// Single fused kernel:
//  - passthrough copy spikes -> out (streaming hints, written-once data)
//  - per-element collector sum -> 5-bin histogram (block -> global atomics)
//  - last-finished block derives all scalar stats and resets the globals.
__global__ void __launch_bounds__(256) hx_fused(
    const float* __restrict__ inF,
    float* __restrict__ outF,
    const int* __restrict__ time_ptr,
    long long N,
    long long out_size)
{
    const int T = (time_ptr != nullptr) ? __ldg(time_ptr) : 4;
    const long long S = N / (long long)T;   // elements per timestep
    const long long gsz = (long long)gridDim.x * blockDim.x;
    const long long tid0 = (long long)blockIdx.x * blockDim.x + threadIdx.x;

    __shared__ unsigned long long sh[8];
    if (threadIdx.x < 8) sh[threadIdx.x] = 0ULL;
    __syncthreads();

    if (T == 4 && (S & 3LL) == 0) {
        // ---- fast path: T=4, float4 vectorized, streaming loads/stores ----
        const float4* __restrict__ in = (const float4*)inF;
        float4* __restrict__ out = (float4*)outF;
        const long long V = S >> 2;  // float4 elements per timestep

        int h0 = 0, h1 = 0, h2 = 0, h3 = 0, h4 = 0;

        for (long long i = tid0; i < V; i += gsz) {
            float4 a = __ldcs(&in[i]);
            float4 b = __ldcs(&in[i + V]);
            float4 c = __ldcs(&in[i + 2 * V]);
            float4 d = __ldcs(&in[i + 3 * V]);
            __stcs(&out[i],         a);
            __stcs(&out[i + V],     b);
            __stcs(&out[i + 2 * V], c);
            __stcs(&out[i + 3 * V], d);

            int s;
            s = (int)(a.x + b.x + c.x + d.x);
            h0 += (s == 0); h1 += (s == 1); h2 += (s == 2); h3 += (s == 3); h4 += (s == 4);
            s = (int)(a.y + b.y + c.y + d.y);
            h0 += (s == 0); h1 += (s == 1); h2 += (s == 2); h3 += (s == 3); h4 += (s == 4);
            s = (int)(a.z + b.z + c.z + d.z);
            h0 += (s == 0); h1 += (s == 1); h2 += (s == 2); h3 += (s == 3); h4 += (s == 4);
            s = (int)(a.w + b.w + c.w + d.w);
            h0 += (s == 0); h1 += (s == 1); h2 += (s == 2); h3 += (s == 3); h4 += (s == 4);
        }

        int hv[5] = {h0, h1, h2, h3, h4};
#pragma unroll
        for (int b = 0; b < 5; ++b) {
            int v = hv[b];
#pragma unroll
            for (int o = 16; o; o >>= 1) v += __shfl_down_sync(0xffffffffu, v, o);
            if ((threadIdx.x & 31) == 0) atomicAdd(&sh[b], (unsigned long long)v);
        }
    } else {
        // ---- generic scalar path (T <= 7) ----
        int h[8];
#pragma unroll
        for (int b = 0; b < 8; ++b) h[b] = 0;

        for (long long i = tid0; i < S; i += gsz) {
            float s = 0.f;
            for (int t = 0; t < T; ++t) {
                float v = __ldcs(&inF[i + (long long)t * S]);
                __stcs(&outF[i + (long long)t * S], v);
                s += v;
            }
            int si = (int)s;
#pragma unroll
            for (int b = 0; b < 8; ++b) h[b] += (si == b);
        }

#pragma unroll
        for (int b = 0; b < 8; ++b) {
            int v = h[b];
#pragma unroll
            for (int o = 16; o; o >>= 1) v += __shfl_down_sync(0xffffffffu, v, o);
            if ((threadIdx.x & 31) == 0) atomicAdd(&sh[b], (unsigned long long)v);
        }
    }

    // Block-level histogram -> global atomics.
    __syncthreads();
    if (threadIdx.x < 8 && sh[threadIdx.x] != 0ULL)
        atomicAdd(&g_hist[threadIdx.x], sh[threadIdx.x]);

    // Make hist (and passthrough stores) globally visible before signaling done.
    __threadfence();

    __shared__ int is_last;
    if (threadIdx.x == 0) {
        unsigned int d = atomicAdd(&g_done, 1u);
        is_last = (d == gridDim.x - 1) ? 1 : 0;
    }
    __syncthreads();

    if (is_last && threadIdx.x == 0) {
        // Read-and-reset so the next graph replay starts from zeros.
        unsigned long long h[8];
#pragma unroll
        for (int k = 0; k < 8; ++k) h[k] = atomicExch(&g_hist[k], 0ULL);
        atomicExch(&g_done, 0u);

        double ones = 0.0;
        for (int k = 0; k <= T && k < 8; ++k) ones += (double)k * (double)h[k];

        if (out_size >= N + (long long)T + 3) {
            // sparsity_ratio = total zero fraction over the whole tensor
            outF[N]     = (float)(((double)N - ones) / (double)N);
            // final-collector zero fraction
            outF[N + 1] = (float)((double)h[0] / (double)S);
            // bincount(collector, length=T+1)
            for (int k = 0; k <= T && k < 8; ++k)
                outF[N + 2 + k] = (float)h[k];
        }
    }
}

extern "C" void kernel_launch(void* const* d_in, const int* in_sizes, int n_in,
                              void* d_out, int out_size)
{
    const float* spikes = (const float*)d_in[0];
    const int* time_ptr = (n_in > 1) ? (const int*)d_in[1] : nullptr;
    const long long N = (long long)in_sizes[0];

    const int threads = 256;
    long long maxItems = (N + 3) / 4;  // upper bound on per-thread work items
    long long want = (maxItems + threads - 1) / threads;
    int blocks = (int)((want < 1184) ? want : 1184);
    if (blocks < 1) blocks = 1;

    hx_fused<<<blocks, threads>>>(spikes, (float*)d_out, time_ptr, N,
                                  (long long)out_size);
}